// round 1
// baseline (speedup 1.0000x reference)
#include <cuda_runtime.h>
#include <math.h>

// GAT layer, fp32 baseline.
// Pipeline:
//   k0: u_src = W_att^T a_src, u_dst = W_att^T a_dst, c_src = b_att.a_src, c_dst = b_att.a_dst
//   k1: h_msg = X @ W1^T + b1 (tiled SGEMM); s_src/s_dst per node; zero h_neigh/denom
//   k2: per edge: w = exp(leaky(s_src[s]+s_dst[d])); atomicAdd(denom[d], w)
//   k3: per edge (1 warp): h_neigh[d] += (w/(denom[d]+1e-9)) * h_msg[s]   (red.global.add.v4.f32)
//   k4: out = leaky((X+h_neigh) + (X*h_neigh) @ W2^T + b2) (tiled SGEMM)

#define MAXN 100032
#define MAXE 1600000

__device__ float g_hmsg[MAXN * 128];
__device__ float g_hneigh[MAXN * 128];
__device__ float g_ssrc[MAXN];
__device__ float g_sdst[MAXN];
__device__ float g_denom[MAXN];
__device__ float g_w[MAXE];
__device__ float g_u[258]; // [0:128) u_src, [128:256) u_dst, [256] c_src, [257] c_dst

__device__ __forceinline__ float leaky_f(float x) { return x >= 0.f ? x : 0.01f * x; }

// ---------------------------------------------------------------------------
// k0: fold the attention GEMM into two 128-vectors + two scalars.
// ---------------------------------------------------------------------------
__global__ void k0_prep(const float* __restrict__ Watt, const float* __restrict__ batt,
                        const float* __restrict__ a)
{
    int k = threadIdx.x; // 0..127
    float us = 0.f, ud = 0.f;
    for (int o = 0; o < 128; o++) {
        float w = Watt[o * 128 + k]; // coalesced across k
        us += w * a[o];
        ud += w * a[128 + o];
    }
    g_u[k] = us;
    g_u[128 + k] = ud;

    __shared__ float red[256];
    red[k] = batt[k] * a[k];
    red[128 + k] = batt[k] * a[128 + k];
    __syncthreads();
    if (k == 0) {
        float cs = 0.f, cd = 0.f;
        for (int i = 0; i < 128; i++) { cs += red[i]; cd += red[128 + i]; }
        g_u[256] = cs;
        g_u[257] = cd;
    }
}

// ---------------------------------------------------------------------------
// k1: h_msg = X @ W1^T + b1 ; s_src/s_dst ; zero h_neigh/denom
// Block: 256 threads, 64 nodes x 128 outs. Thread tile: 4 nodes x 8 outs.
// Shared: Xs[64][132], Wt[128][132] (Wt[k][o] = W1[o][k]).
// ---------------------------------------------------------------------------
#define XS_STRIDE 132
#define K1_SMEM ((64 * XS_STRIDE + 128 * XS_STRIDE) * 4)

__global__ __launch_bounds__(256) void k1_msg(const float* __restrict__ X,
                                              const float* __restrict__ W1,
                                              const float* __restrict__ b1,
                                              int N)
{
    extern __shared__ float sm[];
    float* Xs = sm;                     // 64*132
    float* Wt = sm + 64 * XS_STRIDE;    // 128*132
    const int tid = threadIdx.x;
    const int bn = blockIdx.x * 64;

    // Zero h_neigh rows + denom for this node tile (consumed by k3/k4).
    for (int i = tid; i < 64 * 32; i += 256) {
        int n = bn + (i >> 5);
        if (n < N) ((float4*)g_hneigh)[n * 32 + (i & 31)] = make_float4(0.f, 0.f, 0.f, 0.f);
    }
    if (tid < 64 && bn + tid < N) g_denom[bn + tid] = 0.f;

    // Load X tile (coalesced float4), padded stride 132 (16B-aligned rows).
    for (int i = tid; i < 64 * 32; i += 256) {
        int r = i >> 5, c4 = i & 31;
        int n = bn + r;
        float4 v = (n < N) ? ((const float4*)X)[n * 32 + c4] : make_float4(0.f, 0.f, 0.f, 0.f);
        *(float4*)(Xs + r * XS_STRIDE + c4 * 4) = v;
    }
    // Load W1 transposed: Wt[k*132 + o] = W1[o*128 + k].
    // o varies fastest across lanes -> conflict-free STS (distinct banks).
    for (int i = tid; i < 4096; i += 256) {
        int o = i & 127;
        int k4 = (i >> 7) << 2;
        float4 w = *(const float4*)(W1 + o * 128 + k4);
        Wt[(k4 + 0) * XS_STRIDE + o] = w.x;
        Wt[(k4 + 1) * XS_STRIDE + o] = w.y;
        Wt[(k4 + 2) * XS_STRIDE + o] = w.z;
        Wt[(k4 + 3) * XS_STRIDE + o] = w.w;
    }
    __syncthreads();

    // Per-node attention scalars: 4 threads per node, 32 k each, shfl-reduce.
    {
        int nl = tid >> 2, q = tid & 3;
        const float* xr = Xs + nl * XS_STRIDE + q * 32;
        float as = 0.f, ad = 0.f;
        #pragma unroll
        for (int k = 0; k < 32; k++) {
            float x = xr[k];
            as += x * g_u[q * 32 + k];
            ad += x * g_u[128 + q * 32 + k];
        }
        as += __shfl_down_sync(0xffffffffu, as, 1);
        ad += __shfl_down_sync(0xffffffffu, ad, 1);
        as += __shfl_down_sync(0xffffffffu, as, 2);
        ad += __shfl_down_sync(0xffffffffu, ad, 2);
        if (q == 0 && bn + nl < N) {
            g_ssrc[bn + nl] = as + g_u[256];
            g_sdst[bn + nl] = ad + g_u[257];
        }
    }

    // Main GEMM: acc[m][j] = sum_k X[n0+m][k] * W1[o0+j][k]
    const int tx = tid & 15;   // o0 = tx*8
    const int ty = tid >> 4;   // n0 = ty*4
    float acc[4][8];
    #pragma unroll
    for (int m = 0; m < 4; m++)
        #pragma unroll
        for (int j = 0; j < 8; j++) acc[m][j] = 0.f;

    #pragma unroll 4
    for (int k = 0; k < 128; k++) {
        float4 w0 = *(const float4*)(Wt + k * XS_STRIDE + tx * 8);
        float4 w1 = *(const float4*)(Wt + k * XS_STRIDE + tx * 8 + 4);
        float xm[4];
        #pragma unroll
        for (int m = 0; m < 4; m++) xm[m] = Xs[(ty * 4 + m) * XS_STRIDE + k];
        #pragma unroll
        for (int m = 0; m < 4; m++) {
            acc[m][0] += xm[m] * w0.x; acc[m][1] += xm[m] * w0.y;
            acc[m][2] += xm[m] * w0.z; acc[m][3] += xm[m] * w0.w;
            acc[m][4] += xm[m] * w1.x; acc[m][5] += xm[m] * w1.y;
            acc[m][6] += xm[m] * w1.z; acc[m][7] += xm[m] * w1.w;
        }
    }

    float bb[8];
    #pragma unroll
    for (int j = 0; j < 8; j++) bb[j] = b1[tx * 8 + j];

    #pragma unroll
    for (int m = 0; m < 4; m++) {
        int n = bn + ty * 4 + m;
        if (n < N) {
            float4 r0 = make_float4(acc[m][0] + bb[0], acc[m][1] + bb[1],
                                    acc[m][2] + bb[2], acc[m][3] + bb[3]);
            float4 r1 = make_float4(acc[m][4] + bb[4], acc[m][5] + bb[5],
                                    acc[m][6] + bb[6], acc[m][7] + bb[7]);
            *(float4*)(g_hmsg + n * 128 + tx * 8) = r0;
            *(float4*)(g_hmsg + n * 128 + tx * 8 + 4) = r1;
        }
    }
}

// ---------------------------------------------------------------------------
// k2: edge softmax numerators + denominator accumulation.
// ---------------------------------------------------------------------------
__global__ __launch_bounds__(256) void k2_edge(const int* __restrict__ src,
                                               const int* __restrict__ dst, int E)
{
    int e = blockIdx.x * 256 + threadIdx.x;
    if (e >= E) return;
    int s = src[e];
    int d = dst[e];
    float l = g_ssrc[s] + g_sdst[d];
    l = leaky_f(l);
    float w = expf(l);
    g_w[e] = w;
    atomicAdd(&g_denom[d], w);
}

// ---------------------------------------------------------------------------
// k3: edge aggregation. One warp per edge; one red.global.add.v4.f32 per lane
// covers the full 128-float row in a single warp instruction.
// ---------------------------------------------------------------------------
__global__ __launch_bounds__(256) void k3_agg(const int* __restrict__ src,
                                              const int* __restrict__ dst, int E)
{
    int e = blockIdx.x * 8 + (threadIdx.x >> 5);
    if (e >= E) return;
    int lane = threadIdx.x & 31;
    int s = src[e];
    int d = dst[e];
    float alpha = g_w[e] / (g_denom[d] + 1e-9f);
    float4 v = ((const float4*)g_hmsg)[s * 32 + lane];
    v.x *= alpha; v.y *= alpha; v.z *= alpha; v.w *= alpha;
    float* p = g_hneigh + d * 128 + lane * 4;
    asm volatile("red.global.add.v4.f32 [%0], {%1,%2,%3,%4};"
                 :: "l"(p), "f"(v.x), "f"(v.y), "f"(v.z), "f"(v.w)
                 : "memory");
}

// ---------------------------------------------------------------------------
// k4: out = leaky((X + h_neigh) + (X*h_neigh) @ W2^T + b2)
// Same tiling as k1; two input tiles (sum + product).
// ---------------------------------------------------------------------------
#define K4_SMEM ((2 * 64 * XS_STRIDE + 128 * XS_STRIDE) * 4)

__global__ __launch_bounds__(256) void k4_out(const float* __restrict__ X,
                                              const float* __restrict__ W2,
                                              const float* __restrict__ b2,
                                              float* __restrict__ out, int N)
{
    extern __shared__ float sm[];
    float* Ss = sm;                          // X + h_neigh
    float* Ps = sm + 64 * XS_STRIDE;         // X * h_neigh
    float* Wt = sm + 2 * 64 * XS_STRIDE;     // W2 transposed
    const int tid = threadIdx.x;
    const int bn = blockIdx.x * 64;

    for (int i = tid; i < 64 * 32; i += 256) {
        int r = i >> 5, c4 = i & 31;
        int n = bn + r;
        float4 x = (n < N) ? ((const float4*)X)[n * 32 + c4] : make_float4(0.f, 0.f, 0.f, 0.f);
        float4 h = (n < N) ? ((const float4*)g_hneigh)[n * 32 + c4] : make_float4(0.f, 0.f, 0.f, 0.f);
        *(float4*)(Ss + r * XS_STRIDE + c4 * 4) = make_float4(x.x + h.x, x.y + h.y, x.z + h.z, x.w + h.w);
        *(float4*)(Ps + r * XS_STRIDE + c4 * 4) = make_float4(x.x * h.x, x.y * h.y, x.z * h.z, x.w * h.w);
    }
    for (int i = tid; i < 4096; i += 256) {
        int o = i & 127;
        int k4 = (i >> 7) << 2;
        float4 w = *(const float4*)(W2 + o * 128 + k4);
        Wt[(k4 + 0) * XS_STRIDE + o] = w.x;
        Wt[(k4 + 1) * XS_STRIDE + o] = w.y;
        Wt[(k4 + 2) * XS_STRIDE + o] = w.z;
        Wt[(k4 + 3) * XS_STRIDE + o] = w.w;
    }
    __syncthreads();

    const int tx = tid & 15;
    const int ty = tid >> 4;
    float acc[4][8];
    #pragma unroll
    for (int m = 0; m < 4; m++)
        #pragma unroll
        for (int j = 0; j < 8; j++) acc[m][j] = 0.f;

    #pragma unroll 4
    for (int k = 0; k < 128; k++) {
        float4 w0 = *(const float4*)(Wt + k * XS_STRIDE + tx * 8);
        float4 w1 = *(const float4*)(Wt + k * XS_STRIDE + tx * 8 + 4);
        float pm[4];
        #pragma unroll
        for (int m = 0; m < 4; m++) pm[m] = Ps[(ty * 4 + m) * XS_STRIDE + k];
        #pragma unroll
        for (int m = 0; m < 4; m++) {
            acc[m][0] += pm[m] * w0.x; acc[m][1] += pm[m] * w0.y;
            acc[m][2] += pm[m] * w0.z; acc[m][3] += pm[m] * w0.w;
            acc[m][4] += pm[m] * w1.x; acc[m][5] += pm[m] * w1.y;
            acc[m][6] += pm[m] * w1.z; acc[m][7] += pm[m] * w1.w;
        }
    }

    float bb[8];
    #pragma unroll
    for (int j = 0; j < 8; j++) bb[j] = b2[tx * 8 + j];

    #pragma unroll
    for (int m = 0; m < 4; m++) {
        int n = bn + ty * 4 + m;
        if (n < N) {
            const float* srow = Ss + (ty * 4 + m) * XS_STRIDE + tx * 8;
            float4 r0, r1;
            r0.x = leaky_f(srow[0] + acc[m][0] + bb[0]);
            r0.y = leaky_f(srow[1] + acc[m][1] + bb[1]);
            r0.z = leaky_f(srow[2] + acc[m][2] + bb[2]);
            r0.w = leaky_f(srow[3] + acc[m][3] + bb[3]);
            r1.x = leaky_f(srow[4] + acc[m][4] + bb[4]);
            r1.y = leaky_f(srow[5] + acc[m][5] + bb[5]);
            r1.z = leaky_f(srow[6] + acc[m][6] + bb[6]);
            r1.w = leaky_f(srow[7] + acc[m][7] + bb[7]);
            *(float4*)(out + n * 128 + tx * 8) = r0;
            *(float4*)(out + n * 128 + tx * 8 + 4) = r1;
        }
    }
}

// ---------------------------------------------------------------------------
// Launch. Inputs (metadata order): indices, features, num_nodes, W_att_w,
// W_att_b, W1_w, W1_b, W2_w, W2_b, a
// ---------------------------------------------------------------------------
extern "C" void kernel_launch(void* const* d_in, const int* in_sizes, int n_in,
                              void* d_out, int out_size)
{
    const int*   indices = (const int*)d_in[0];
    const float* X       = (const float*)d_in[1];
    const float* Watt    = (const float*)d_in[3];
    const float* batt    = (const float*)d_in[4];
    const float* W1      = (const float*)d_in[5];
    const float* b1      = (const float*)d_in[6];
    const float* W2      = (const float*)d_in[7];
    const float* b2      = (const float*)d_in[8];
    const float* a       = (const float*)d_in[9];
    float* out = (float*)d_out;

    const int E = in_sizes[0] / 2;
    const int N = in_sizes[1] / 128;
    const int* src = indices;
    const int* dst = indices + E;

    cudaFuncSetAttribute(k1_msg, cudaFuncAttributeMaxDynamicSharedMemorySize, K1_SMEM);
    cudaFuncSetAttribute(k4_out, cudaFuncAttributeMaxDynamicSharedMemorySize, K4_SMEM);

    k0_prep<<<1, 128>>>(Watt, batt, a);
    k1_msg<<<(N + 63) / 64, 256, K1_SMEM>>>(X, W1, b1, N);
    k2_edge<<<(E + 255) / 256, 256>>>(src, dst, E);
    k3_agg<<<(E + 7) / 8, 256>>>(src, dst, E);
    k4_out<<<(N + 63) / 64, 256, K4_SMEM>>>(X, W2, b2, out, N);
}

// round 2
// speedup vs baseline: 1.2835x; 1.2835x over previous
#include <cuda_runtime.h>
#include <math.h>

// GAT layer, fp32.
//   k0: fold attention GEMM into u_src/u_dst vectors + scalars
//   k1: h_msg = X @ W1^T + b1 (128x128 tile, 8x8 microtile); s_src/s_dst; zero hneigh/denom
//   k2: per edge: w = exp(leaky(s_src[s]+s_dst[d])); red(denom[d], w)
//   k3: 8 edges/warp batched gathers -> red.global.add.v4 into h_neigh
//   k4: out = leaky((X+h_neigh) + (X*h_neigh) @ W2^T + b2)

#define MAXN 100096
#define MAXE 1600000
#define TS 132

__device__ float g_hmsg[MAXN * 128];
__device__ float g_hneigh[MAXN * 128];
__device__ float g_ssrc[MAXN];
__device__ float g_sdst[MAXN];
__device__ float g_denom[MAXN];
__device__ float g_w[MAXE];
__device__ float g_u[258]; // [0:128) u_src, [128:256) u_dst, [256] c_src, [257] c_dst

__device__ __forceinline__ float leaky_f(float x) { return x >= 0.f ? x : 0.01f * x; }

// ---------------------------------------------------------------------------
__global__ void k0_prep(const float* __restrict__ Watt, const float* __restrict__ batt,
                        const float* __restrict__ a)
{
    int k = threadIdx.x; // 0..127
    float us = 0.f, ud = 0.f;
    for (int o = 0; o < 128; o++) {
        float w = Watt[o * 128 + k];
        us += w * a[o];
        ud += w * a[128 + o];
    }
    g_u[k] = us;
    g_u[128 + k] = ud;

    __shared__ float red[256];
    red[k] = batt[k] * a[k];
    red[128 + k] = batt[k] * a[128 + k];
    __syncthreads();
    if (k == 0) {
        float cs = 0.f, cd = 0.f;
        for (int i = 0; i < 128; i++) { cs += red[i]; cd += red[128 + i]; }
        g_u[256] = cs;
        g_u[257] = cd;
    }
}

// ---------------------------------------------------------------------------
// k1: 128 nodes x 128 outs per block, 256 threads, 8x8 per thread.
// Xs node-major [128][TS]; Wt k-major [128][TS] (Wt[k][o] = W1[o][k]).
// ---------------------------------------------------------------------------
#define GEMM_SMEM ((128 * TS + 128 * TS) * 4)

__global__ __launch_bounds__(256) void k1_msg(const float* __restrict__ X,
                                              const float* __restrict__ W1,
                                              const float* __restrict__ b1,
                                              int N)
{
    extern __shared__ float sm[];
    float* Xs = sm;              // 128*TS, node-major
    float* Wt = sm + 128 * TS;   // 128*TS, k-major
    const int tid = threadIdx.x;
    const int bn = blockIdx.x * 128;

    // Zero h_neigh rows + denom for this node tile.
    for (int i = tid; i < 128 * 32; i += 256) {
        int n = bn + (i >> 5);
        if (n < N) ((float4*)g_hneigh)[n * 32 + (i & 31)] = make_float4(0.f, 0.f, 0.f, 0.f);
    }
    if (tid < 128 && bn + tid < N) g_denom[bn + tid] = 0.f;

    // Load X tile coalesced.
    for (int i = tid; i < 128 * 32; i += 256) {
        int r = i >> 5, c4 = i & 31;
        int n = bn + r;
        float4 v = (n < N) ? ((const float4*)X)[n * 32 + c4] : make_float4(0.f, 0.f, 0.f, 0.f);
        *(float4*)(Xs + r * TS + c4 * 4) = v;
    }
    // Load W1 transposed (o fastest across lanes -> conflict-free STS).
    for (int i = tid; i < 4096; i += 256) {
        int o = i & 127;
        int k4 = (i >> 7) << 2;
        float4 w = *(const float4*)(W1 + o * 128 + k4);
        Wt[(k4 + 0) * TS + o] = w.x;
        Wt[(k4 + 1) * TS + o] = w.y;
        Wt[(k4 + 2) * TS + o] = w.z;
        Wt[(k4 + 3) * TS + o] = w.w;
    }
    __syncthreads();

    // Attention scalars: 2 threads per node, 64 k each + 1 shfl.
    {
        int nl = tid >> 1, q = tid & 1;
        const float* xr = Xs + nl * TS + q * 64;
        float as = 0.f, ad = 0.f;
        #pragma unroll
        for (int k = 0; k < 64; k++) {
            float x = xr[k];
            as += x * g_u[q * 64 + k];
            ad += x * g_u[128 + q * 64 + k];
        }
        as += __shfl_down_sync(0xffffffffu, as, 1);
        ad += __shfl_down_sync(0xffffffffu, ad, 1);
        if (q == 0 && bn + nl < N) {
            g_ssrc[bn + nl] = as + g_u[256];
            g_sdst[bn + nl] = ad + g_u[257];
        }
    }

    const int tx = tid & 15;   // outs: tx*8
    const int ty = tid >> 4;   // nodes: ty*8
    float acc[8][8];
    #pragma unroll
    for (int m = 0; m < 8; m++)
        #pragma unroll
        for (int j = 0; j < 8; j++) acc[m][j] = 0.f;

    const float* xb = Xs + ty * 8 * TS;
    const float* wb = Wt + tx * 8;

    #pragma unroll 2
    for (int k = 0; k < 128; k += 4) {
        float4 xv[8];
        #pragma unroll
        for (int m = 0; m < 8; m++) xv[m] = *(const float4*)(xb + m * TS + k);
        #pragma unroll
        for (int kk = 0; kk < 4; kk++) {
            float4 w0 = *(const float4*)(wb + (k + kk) * TS);
            float4 w1 = *(const float4*)(wb + (k + kk) * TS + 4);
            #pragma unroll
            for (int m = 0; m < 8; m++) {
                float x = (&xv[m].x)[kk];
                acc[m][0] += x * w0.x; acc[m][1] += x * w0.y;
                acc[m][2] += x * w0.z; acc[m][3] += x * w0.w;
                acc[m][4] += x * w1.x; acc[m][5] += x * w1.y;
                acc[m][6] += x * w1.z; acc[m][7] += x * w1.w;
            }
        }
    }

    float bb[8];
    #pragma unroll
    for (int j = 0; j < 8; j++) bb[j] = __ldg(b1 + tx * 8 + j);

    #pragma unroll
    for (int m = 0; m < 8; m++) {
        int n = bn + ty * 8 + m;
        if (n < N) {
            float4 r0 = make_float4(acc[m][0] + bb[0], acc[m][1] + bb[1],
                                    acc[m][2] + bb[2], acc[m][3] + bb[3]);
            float4 r1 = make_float4(acc[m][4] + bb[4], acc[m][5] + bb[5],
                                    acc[m][6] + bb[6], acc[m][7] + bb[7]);
            *(float4*)(g_hmsg + n * 128 + tx * 8) = r0;
            *(float4*)(g_hmsg + n * 128 + tx * 8 + 4) = r1;
        }
    }
}

// ---------------------------------------------------------------------------
__global__ __launch_bounds__(256) void k2_edge(const int* __restrict__ src,
                                               const int* __restrict__ dst, int E)
{
    int e = blockIdx.x * 256 + threadIdx.x;
    if (e >= E) return;
    int s = src[e];
    int d = dst[e];
    float w = expf(leaky_f(g_ssrc[s] + g_sdst[d]));
    g_w[e] = w;
    atomicAdd(&g_denom[d], w);
}

// ---------------------------------------------------------------------------
// k3: block = 256 threads = 8 warps handles 64 edges; 8 edges per warp.
// Stage (src,dst,alpha) in smem, then 8 independent gathers -> 8 reds.
// ---------------------------------------------------------------------------
__global__ __launch_bounds__(256) void k3_agg(const int* __restrict__ src,
                                              const int* __restrict__ dst, int E)
{
    __shared__ int ss[64];
    __shared__ int sd[64];
    __shared__ float sa[64];
    const int tid = threadIdx.x;
    const int e0 = blockIdx.x * 64;

    if (tid < 64) {
        int e = e0 + tid;
        if (e < E) {
            int d = dst[e];
            ss[tid] = src[e];
            sd[tid] = d;
            sa[tid] = g_w[e] / (g_denom[d] + 1e-9f);
        }
    }
    __syncthreads();

    const int warp = tid >> 5;
    const int lane = tid & 31;
    const int base = warp * 8;

    if (e0 + base + 7 < E) {
        float4 v[8];
        #pragma unroll
        for (int i = 0; i < 8; i++)
            v[i] = ((const float4*)g_hmsg)[ss[base + i] * 32 + lane];
        #pragma unroll
        for (int i = 0; i < 8; i++) {
            float a = sa[base + i];
            float* p = g_hneigh + sd[base + i] * 128 + lane * 4;
            asm volatile("red.global.add.v4.f32 [%0], {%1,%2,%3,%4};"
                         :: "l"(p), "f"(a * v[i].x), "f"(a * v[i].y),
                            "f"(a * v[i].z), "f"(a * v[i].w)
                         : "memory");
        }
    } else {
        for (int i = 0; i < 8; i++) {
            if (e0 + base + i < E) {
                float a = sa[base + i];
                float4 v = ((const float4*)g_hmsg)[ss[base + i] * 32 + lane];
                float* p = g_hneigh + sd[base + i] * 128 + lane * 4;
                asm volatile("red.global.add.v4.f32 [%0], {%1,%2,%3,%4};"
                             :: "l"(p), "f"(a * v.x), "f"(a * v.y),
                                "f"(a * v.z), "f"(a * v.w)
                             : "memory");
            }
        }
    }
}

// ---------------------------------------------------------------------------
// k4: out = leaky((X+h) + (X*h) @ W2^T + b2). Ps tile in smem; (X+h) reloaded
// from gmem in the epilogue (L2-hot) to keep smem at 2 tiles.
// ---------------------------------------------------------------------------
__global__ __launch_bounds__(256) void k4_out(const float* __restrict__ X,
                                              const float* __restrict__ W2,
                                              const float* __restrict__ b2,
                                              float* __restrict__ out, int N)
{
    extern __shared__ float sm[];
    float* Ps = sm;              // X * h_neigh, node-major
    float* Wt = sm + 128 * TS;   // W2 k-major
    const int tid = threadIdx.x;
    const int bn = blockIdx.x * 128;

    for (int i = tid; i < 128 * 32; i += 256) {
        int r = i >> 5, c4 = i & 31;
        int n = bn + r;
        float4 x = (n < N) ? ((const float4*)X)[n * 32 + c4] : make_float4(0.f, 0.f, 0.f, 0.f);
        float4 h = (n < N) ? ((const float4*)g_hneigh)[n * 32 + c4] : make_float4(0.f, 0.f, 0.f, 0.f);
        *(float4*)(Ps + r * TS + c4 * 4) = make_float4(x.x * h.x, x.y * h.y, x.z * h.z, x.w * h.w);
    }
    for (int i = tid; i < 4096; i += 256) {
        int o = i & 127;
        int k4 = (i >> 7) << 2;
        float4 w = *(const float4*)(W2 + o * 128 + k4);
        Wt[(k4 + 0) * TS + o] = w.x;
        Wt[(k4 + 1) * TS + o] = w.y;
        Wt[(k4 + 2) * TS + o] = w.z;
        Wt[(k4 + 3) * TS + o] = w.w;
    }
    __syncthreads();

    const int tx = tid & 15;
    const int ty = tid >> 4;
    float acc[8][8];
    #pragma unroll
    for (int m = 0; m < 8; m++)
        #pragma unroll
        for (int j = 0; j < 8; j++) acc[m][j] = 0.f;

    const float* pb = Ps + ty * 8 * TS;
    const float* wb = Wt + tx * 8;

    #pragma unroll 2
    for (int k = 0; k < 128; k += 4) {
        float4 xv[8];
        #pragma unroll
        for (int m = 0; m < 8; m++) xv[m] = *(const float4*)(pb + m * TS + k);
        #pragma unroll
        for (int kk = 0; kk < 4; kk++) {
            float4 w0 = *(const float4*)(wb + (k + kk) * TS);
            float4 w1 = *(const float4*)(wb + (k + kk) * TS + 4);
            #pragma unroll
            for (int m = 0; m < 8; m++) {
                float x = (&xv[m].x)[kk];
                acc[m][0] += x * w0.x; acc[m][1] += x * w0.y;
                acc[m][2] += x * w0.z; acc[m][3] += x * w0.w;
                acc[m][4] += x * w1.x; acc[m][5] += x * w1.y;
                acc[m][6] += x * w1.z; acc[m][7] += x * w1.w;
            }
        }
    }

    float bb[8];
    #pragma unroll
    for (int j = 0; j < 8; j++) bb[j] = __ldg(b2 + tx * 8 + j);

    #pragma unroll
    for (int m = 0; m < 8; m++) {
        int n = bn + ty * 8 + m;
        if (n < N) {
            float4 x0 = *(const float4*)(X + n * 128 + tx * 8);
            float4 x1 = *(const float4*)(X + n * 128 + tx * 8 + 4);
            float4 h0 = *(const float4*)(g_hneigh + n * 128 + tx * 8);
            float4 h1 = *(const float4*)(g_hneigh + n * 128 + tx * 8 + 4);
            float4 r0, r1;
            r0.x = leaky_f(x0.x + h0.x + acc[m][0] + bb[0]);
            r0.y = leaky_f(x0.y + h0.y + acc[m][1] + bb[1]);
            r0.z = leaky_f(x0.z + h0.z + acc[m][2] + bb[2]);
            r0.w = leaky_f(x0.w + h0.w + acc[m][3] + bb[3]);
            r1.x = leaky_f(x1.x + h1.x + acc[m][4] + bb[4]);
            r1.y = leaky_f(x1.y + h1.y + acc[m][5] + bb[5]);
            r1.z = leaky_f(x1.z + h1.z + acc[m][6] + bb[6]);
            r1.w = leaky_f(x1.w + h1.w + acc[m][7] + bb[7]);
            *(float4*)(out + n * 128 + tx * 8) = r0;
            *(float4*)(out + n * 128 + tx * 8 + 4) = r1;
        }
    }
}

// ---------------------------------------------------------------------------
extern "C" void kernel_launch(void* const* d_in, const int* in_sizes, int n_in,
                              void* d_out, int out_size)
{
    const int*   indices = (const int*)d_in[0];
    const float* X       = (const float*)d_in[1];
    const float* Watt    = (const float*)d_in[3];
    const float* batt    = (const float*)d_in[4];
    const float* W1      = (const float*)d_in[5];
    const float* b1      = (const float*)d_in[6];
    const float* W2      = (const float*)d_in[7];
    const float* b2      = (const float*)d_in[8];
    const float* a       = (const float*)d_in[9];
    float* out = (float*)d_out;

    const int E = in_sizes[0] / 2;
    const int N = in_sizes[1] / 128;
    const int* src = indices;
    const int* dst = indices + E;

    cudaFuncSetAttribute(k1_msg, cudaFuncAttributeMaxDynamicSharedMemorySize, GEMM_SMEM);
    cudaFuncSetAttribute(k4_out, cudaFuncAttributeMaxDynamicSharedMemorySize, GEMM_SMEM);

    k0_prep<<<1, 128>>>(Watt, batt, a);
    k1_msg<<<(N + 127) / 128, 256, GEMM_SMEM>>>(X, W1, b1, N);
    k2_edge<<<(E + 255) / 256, 256>>>(src, dst, E);
    k3_agg<<<(E + 63) / 64, 256>>>(src, dst, E);
    k4_out<<<(N + 127) / 128, 256, GEMM_SMEM>>>(X, W2, b2, out, N);
}

// round 3
// speedup vs baseline: 1.7221x; 1.3418x over previous
#include <cuda_runtime.h>
#include <math.h>
#include <stdint.h>

// GAT layer. Pipeline:
//   k0:      fold attention GEMM into u_src/u_dst + scalars
//   kz/kh/scanA/scanB/scanC/kscat: counting-sort edges by dst (CSR)
//   k1:      h_msg = X @ W1^T + b1 (tf32 mma); s_src/s_dst (fp32)
//   kagg:    warp-per-node fused softmax+aggregate -> h_neigh (no atomics)
//   k4:      out = leaky((X+h) + (X*h) @ W2^T + b2) (tf32 mma)

#define MAXN 100096
#define MAXE 1600000
#define TS 132

__device__ float g_hmsg[MAXN * 128];
__device__ float g_hneigh[MAXN * 128];
__device__ float g_ssrc[MAXN];
__device__ float g_sdst[MAXN];
__device__ float g_u[258];
__device__ int   g_cnt[MAXN];
__device__ int   g_off[MAXN + 1];
__device__ int   g_cur[MAXN];
__device__ int   g_es[MAXE];     // src sorted by dst
__device__ int   g_btot[128];
__device__ int   g_bex[128];

__device__ __forceinline__ float leaky_f(float x) { return x >= 0.f ? x : 0.01f * x; }

__device__ __forceinline__ uint32_t f2tf(float f) {
    uint32_t u;
    asm("cvt.rna.tf32.f32 %0, %1;" : "=r"(u) : "f"(f));
    return u;
}

#define MMA_TF32(c, a, b0, b1)                                                   \
    asm volatile("mma.sync.aligned.m16n8k8.row.col.f32.tf32.tf32.f32 "           \
                 "{%0,%1,%2,%3}, {%4,%5,%6,%7}, {%8,%9}, {%0,%1,%2,%3};"         \
                 : "+f"((c)[0]), "+f"((c)[1]), "+f"((c)[2]), "+f"((c)[3])        \
                 : "r"((a)[0]), "r"((a)[1]), "r"((a)[2]), "r"((a)[3]),           \
                   "r"(b0), "r"(b1))

// ---------------------------------------------------------------------------
__global__ void k0_prep(const float* __restrict__ Watt, const float* __restrict__ batt,
                        const float* __restrict__ a)
{
    int k = threadIdx.x;
    float us = 0.f, ud = 0.f;
    for (int o = 0; o < 128; o++) {
        float w = Watt[o * 128 + k];
        us += w * a[o];
        ud += w * a[128 + o];
    }
    g_u[k] = us;
    g_u[128 + k] = ud;

    __shared__ float red[256];
    red[k] = batt[k] * a[k];
    red[128 + k] = batt[k] * a[128 + k];
    __syncthreads();
    if (k == 0) {
        float cs = 0.f, cd = 0.f;
        for (int i = 0; i < 128; i++) { cs += red[i]; cd += red[128 + i]; }
        g_u[256] = cs;
        g_u[257] = cd;
    }
}

// --------------------------- counting sort by dst ---------------------------
__global__ void kz(int N)
{
    int i = blockIdx.x * 256 + threadIdx.x;
    if (i < N) g_cnt[i] = 0;
}

__global__ void kh(const int* __restrict__ dst, int E)
{
    int e = blockIdx.x * 256 + threadIdx.x;
    if (e < E) atomicAdd(&g_cnt[__ldg(dst + e)], 1);
}

__global__ __launch_bounds__(1024) void scanA(int N)
{
    __shared__ int sh[1024];
    int tid = threadIdx.x;
    int g = blockIdx.x * 1024 + tid;
    int v = (g < N) ? g_cnt[g] : 0;
    sh[tid] = v;
    __syncthreads();
    for (int d = 1; d < 1024; d <<= 1) {
        int t = (tid >= d) ? sh[tid - d] : 0;
        __syncthreads();
        sh[tid] += t;
        __syncthreads();
    }
    if (g < N) g_off[g] = sh[tid] - v;   // exclusive within block
    if (tid == 1023) g_btot[blockIdx.x] = sh[1023];
}

__global__ void scanB(int N, int NB)
{
    __shared__ int s[128];
    int tid = threadIdx.x;
    if (tid < NB) s[tid] = g_btot[tid];
    __syncthreads();
    if (tid == 0) {
        int run = 0;
        for (int i = 0; i < NB; i++) { int c = s[i]; s[i] = run; run += c; }
        g_off[N] = run;
    }
    __syncthreads();
    if (tid < NB) g_bex[tid] = s[tid];
}

__global__ __launch_bounds__(1024) void scanC(int N)
{
    int g = blockIdx.x * 1024 + threadIdx.x;
    if (g < N) {
        int o = g_off[g] + g_bex[blockIdx.x];
        g_off[g] = o;
        g_cur[g] = o;
    }
}

__global__ void kscat(const int* __restrict__ src, const int* __restrict__ dst, int E)
{
    int e = blockIdx.x * 256 + threadIdx.x;
    if (e < E) {
        int d = __ldg(dst + e);
        int pos = atomicAdd(&g_cur[d], 1);
        g_es[pos] = __ldg(src + e);
    }
}

// ---------------------------------------------------------------------------
// tf32 GEMM core: 128x128 tile, 8 warps (4m x 2n), warp tile 32x64.
// Xs/Ws fp32 in smem, stride TS (conflict-free fragment loads).
// ---------------------------------------------------------------------------
#define GEMM_SMEM ((128 * TS + 128 * TS) * 4)

__global__ __launch_bounds__(256) void k1_msg(const float* __restrict__ X,
                                              const float* __restrict__ W1,
                                              const float* __restrict__ b1,
                                              int N)
{
    extern __shared__ float sm[];
    float* Xs = sm;
    float* Ws = sm + 128 * TS;
    const int tid = threadIdx.x;
    const int bn = blockIdx.x * 128;

    for (int i = tid; i < 128 * 32; i += 256) {
        int r = i >> 5, c4 = i & 31;
        int n = bn + r;
        float4 v = (n < N) ? ((const float4*)X)[n * 32 + c4] : make_float4(0.f, 0.f, 0.f, 0.f);
        *(float4*)(Xs + r * TS + c4 * 4) = v;
    }
    for (int i = tid; i < 128 * 32; i += 256) {
        int o = i >> 5, q = i & 31;
        float4 w = *(const float4*)(W1 + o * 128 + q * 4);
        *(float4*)(Ws + o * TS + q * 4) = w;
    }
    __syncthreads();

    // attention scalars (fp32 exact)
    {
        int nl = tid >> 1, q = tid & 1;
        const float* xr = Xs + nl * TS + q * 64;
        float as = 0.f, ad = 0.f;
        #pragma unroll
        for (int k = 0; k < 64; k++) {
            float x = xr[k];
            as += x * g_u[q * 64 + k];
            ad += x * g_u[128 + q * 64 + k];
        }
        as += __shfl_down_sync(0xffffffffu, as, 1);
        ad += __shfl_down_sync(0xffffffffu, ad, 1);
        if (q == 0 && bn + nl < N) {
            g_ssrc[bn + nl] = as + g_u[256];
            g_sdst[bn + nl] = ad + g_u[257];
        }
    }

    const int wid = tid >> 5, lane = tid & 31;
    const int gid = lane >> 2, tig = lane & 3;
    const int mb = (wid >> 1) * 32;
    const int nb = (wid & 1) * 64;

    float acc[2][8][4];
    #pragma unroll
    for (int m = 0; m < 2; m++)
        #pragma unroll
        for (int n = 0; n < 8; n++)
            #pragma unroll
            for (int j = 0; j < 4; j++) acc[m][n][j] = 0.f;

    #pragma unroll 4
    for (int ks = 0; ks < 16; ks++) {
        int k0 = ks * 8;
        uint32_t a[2][4];
        #pragma unroll
        for (int mt = 0; mt < 2; mt++) {
            int r0 = mb + mt * 16 + gid;
            a[mt][0] = f2tf(Xs[r0 * TS + k0 + tig]);
            a[mt][1] = f2tf(Xs[(r0 + 8) * TS + k0 + tig]);
            a[mt][2] = f2tf(Xs[r0 * TS + k0 + tig + 4]);
            a[mt][3] = f2tf(Xs[(r0 + 8) * TS + k0 + tig + 4]);
        }
        #pragma unroll
        for (int nt = 0; nt < 8; nt++) {
            int o = nb + nt * 8 + gid;
            uint32_t b0 = f2tf(Ws[o * TS + k0 + tig]);
            uint32_t b1v = f2tf(Ws[o * TS + k0 + tig + 4]);
            MMA_TF32(acc[0][nt], a[0], b0, b1v);
            MMA_TF32(acc[1][nt], a[1], b0, b1v);
        }
    }

    #pragma unroll
    for (int nt = 0; nt < 8; nt++) {
        int col = nb + nt * 8 + tig * 2;
        float2 bb = *(const float2*)(b1 + col);
        #pragma unroll
        for (int mt = 0; mt < 2; mt++) {
            int row = bn + mb + mt * 16 + gid;
            if (row < N)
                *(float2*)(g_hmsg + row * 128 + col) =
                    make_float2(acc[mt][nt][0] + bb.x, acc[mt][nt][1] + bb.y);
            if (row + 8 < N)
                *(float2*)(g_hmsg + (row + 8) * 128 + col) =
                    make_float2(acc[mt][nt][2] + bb.x, acc[mt][nt][3] + bb.y);
        }
    }
}

// ---------------------------------------------------------------------------
// kagg: one warp per dst node; fused softmax + aggregation, single store.
// ---------------------------------------------------------------------------
__global__ __launch_bounds__(256) void kagg(int N)
{
    const int d = blockIdx.x * 8 + (threadIdx.x >> 5);
    if (d >= N) return;
    const int lane = threadIdx.x & 31;
    const int rs = g_off[d], re = g_off[d + 1];
    const float sdst_d = g_sdst[d];

    float4 acc = make_float4(0.f, 0.f, 0.f, 0.f);
    float wsum = 0.f;

    for (int c = rs; c < re; c += 32) {
        int nrem = re - c;
        int cnt = nrem < 32 ? nrem : 32;
        int s = (lane < cnt) ? g_es[c + lane] : 0;
        float w = 0.f;
        if (lane < cnt) w = expf(leaky_f(g_ssrc[s] + sdst_d));
        wsum += w;

        int j = 0;
        for (; j + 4 <= cnt; j += 4) {
            int s0 = __shfl_sync(0xffffffffu, s, j);
            int s1 = __shfl_sync(0xffffffffu, s, j + 1);
            int s2 = __shfl_sync(0xffffffffu, s, j + 2);
            int s3 = __shfl_sync(0xffffffffu, s, j + 3);
            float w0 = __shfl_sync(0xffffffffu, w, j);
            float w1 = __shfl_sync(0xffffffffu, w, j + 1);
            float w2 = __shfl_sync(0xffffffffu, w, j + 2);
            float w3 = __shfl_sync(0xffffffffu, w, j + 3);
            float4 v0 = ((const float4*)g_hmsg)[s0 * 32 + lane];
            float4 v1 = ((const float4*)g_hmsg)[s1 * 32 + lane];
            float4 v2 = ((const float4*)g_hmsg)[s2 * 32 + lane];
            float4 v3 = ((const float4*)g_hmsg)[s3 * 32 + lane];
            acc.x += w0 * v0.x + w1 * v1.x + w2 * v2.x + w3 * v3.x;
            acc.y += w0 * v0.y + w1 * v1.y + w2 * v2.y + w3 * v3.y;
            acc.z += w0 * v0.z + w1 * v1.z + w2 * v2.z + w3 * v3.z;
            acc.w += w0 * v0.w + w1 * v1.w + w2 * v2.w + w3 * v3.w;
        }
        for (; j < cnt; j++) {
            int sj = __shfl_sync(0xffffffffu, s, j);
            float wj = __shfl_sync(0xffffffffu, w, j);
            float4 v = ((const float4*)g_hmsg)[sj * 32 + lane];
            acc.x += wj * v.x; acc.y += wj * v.y;
            acc.z += wj * v.z; acc.w += wj * v.w;
        }
    }

    #pragma unroll
    for (int o = 16; o > 0; o >>= 1) wsum += __shfl_xor_sync(0xffffffffu, wsum, o);
    float inv = 1.f / (wsum + 1e-9f);
    acc.x *= inv; acc.y *= inv; acc.z *= inv; acc.w *= inv;
    ((float4*)g_hneigh)[d * 32 + lane] = acc;
}

// ---------------------------------------------------------------------------
__global__ __launch_bounds__(256) void k4_out(const float* __restrict__ X,
                                              const float* __restrict__ W2,
                                              const float* __restrict__ b2,
                                              float* __restrict__ out, int N)
{
    extern __shared__ float sm[];
    float* Ps = sm;
    float* Ws = sm + 128 * TS;
    const int tid = threadIdx.x;
    const int bn = blockIdx.x * 128;

    for (int i = tid; i < 128 * 32; i += 256) {
        int r = i >> 5, c4 = i & 31;
        int n = bn + r;
        float4 x = (n < N) ? ((const float4*)X)[n * 32 + c4] : make_float4(0.f, 0.f, 0.f, 0.f);
        float4 h = (n < N) ? ((const float4*)g_hneigh)[n * 32 + c4] : make_float4(0.f, 0.f, 0.f, 0.f);
        *(float4*)(Ps + r * TS + c4 * 4) = make_float4(x.x * h.x, x.y * h.y, x.z * h.z, x.w * h.w);
    }
    for (int i = tid; i < 128 * 32; i += 256) {
        int o = i >> 5, q = i & 31;
        float4 w = *(const float4*)(W2 + o * 128 + q * 4);
        *(float4*)(Ws + o * TS + q * 4) = w;
    }
    __syncthreads();

    const int wid = tid >> 5, lane = tid & 31;
    const int gid = lane >> 2, tig = lane & 3;
    const int mb = (wid >> 1) * 32;
    const int nb = (wid & 1) * 64;

    float acc[2][8][4];
    #pragma unroll
    for (int m = 0; m < 2; m++)
        #pragma unroll
        for (int n = 0; n < 8; n++)
            #pragma unroll
            for (int j = 0; j < 4; j++) acc[m][n][j] = 0.f;

    #pragma unroll 4
    for (int ks = 0; ks < 16; ks++) {
        int k0 = ks * 8;
        uint32_t a[2][4];
        #pragma unroll
        for (int mt = 0; mt < 2; mt++) {
            int r0 = mb + mt * 16 + gid;
            a[mt][0] = f2tf(Ps[r0 * TS + k0 + tig]);
            a[mt][1] = f2tf(Ps[(r0 + 8) * TS + k0 + tig]);
            a[mt][2] = f2tf(Ps[r0 * TS + k0 + tig + 4]);
            a[mt][3] = f2tf(Ps[(r0 + 8) * TS + k0 + tig + 4]);
        }
        #pragma unroll
        for (int nt = 0; nt < 8; nt++) {
            int o = nb + nt * 8 + gid;
            uint32_t b0 = f2tf(Ws[o * TS + k0 + tig]);
            uint32_t b1v = f2tf(Ws[o * TS + k0 + tig + 4]);
            MMA_TF32(acc[0][nt], a[0], b0, b1v);
            MMA_TF32(acc[1][nt], a[1], b0, b1v);
        }
    }

    #pragma unroll
    for (int nt = 0; nt < 8; nt++) {
        int col = nb + nt * 8 + tig * 2;
        float2 bb = *(const float2*)(b2 + col);
        #pragma unroll
        for (int mt = 0; mt < 2; mt++) {
            #pragma unroll
            for (int half = 0; half < 2; half++) {
                int row = bn + mb + mt * 16 + gid + half * 8;
                if (row < N) {
                    float2 x = *(const float2*)(X + row * 128 + col);
                    float2 h = *(const float2*)(g_hneigh + row * 128 + col);
                    float r0 = x.x + h.x + acc[mt][nt][half * 2] + bb.x;
                    float r1 = x.y + h.y + acc[mt][nt][half * 2 + 1] + bb.y;
                    *(float2*)(out + row * 128 + col) =
                        make_float2(leaky_f(r0), leaky_f(r1));
                }
            }
        }
    }
}

// ---------------------------------------------------------------------------
extern "C" void kernel_launch(void* const* d_in, const int* in_sizes, int n_in,
                              void* d_out, int out_size)
{
    const int*   indices = (const int*)d_in[0];
    const float* X       = (const float*)d_in[1];
    const float* Watt    = (const float*)d_in[3];
    const float* batt    = (const float*)d_in[4];
    const float* W1      = (const float*)d_in[5];
    const float* b1      = (const float*)d_in[6];
    const float* W2      = (const float*)d_in[7];
    const float* b2      = (const float*)d_in[8];
    const float* a       = (const float*)d_in[9];
    float* out = (float*)d_out;

    const int E = in_sizes[0] / 2;
    const int N = in_sizes[1] / 128;
    const int* src = indices;
    const int* dst = indices + E;
    const int NB = (N + 1023) / 1024;

    cudaFuncSetAttribute(k1_msg, cudaFuncAttributeMaxDynamicSharedMemorySize, GEMM_SMEM);
    cudaFuncSetAttribute(k4_out, cudaFuncAttributeMaxDynamicSharedMemorySize, GEMM_SMEM);

    k0_prep<<<1, 128>>>(Watt, batt, a);
    kz<<<(N + 255) / 256, 256>>>(N);
    kh<<<(E + 255) / 256, 256>>>(dst, E);
    scanA<<<NB, 1024>>>(N);
    scanB<<<1, 128>>>(N, NB);
    scanC<<<NB, 1024>>>(N);
    kscat<<<(E + 255) / 256, 256>>>(src, dst, E);
    k1_msg<<<(N + 127) / 128, 256, GEMM_SMEM>>>(X, W1, b1, N);
    kagg<<<(N + 7) / 8, 256>>>(N);
    k4_out<<<(N + 127) / 128, 256, GEMM_SMEM>>>(X, W2, b2, out, N);
}

// round 4
// speedup vs baseline: 2.0179x; 1.1718x over previous
#include <cuda_runtime.h>
#include <cuda_fp16.h>
#include <math.h>
#include <stdint.h>

// GAT layer.
//   k0:    fold attention GEMM into u_src/u_dst + scalars
//   kz/kh/scanA/scanB/scanC/kscat: counting-sort edges by dst (CSR)
//   ks:    s_src/s_dst per node (warp per node, fp32)
//   k1:    h_msg = X @ W1^T + b1 (tf32 mma, fragment-ordered smem) -> fp16
//   kagg:  warp-per-node fused softmax+aggregate (fp16 gather, fp32 accum)
//   k4:    out = leaky((X+h) + (X*h) @ W2^T + b2) (tf32 mma)

#define MAXN 100096
#define MAXE 1600000
#define TS 132

__device__ __half g_hmsg[MAXN * 128];
__device__ float  g_hneigh[MAXN * 128];
__device__ float  g_ssrc[MAXN];
__device__ float  g_sdst[MAXN];
__device__ __align__(16) float g_u[260];
__device__ int    g_cnt[MAXN];
__device__ int    g_off[MAXN + 1];
__device__ int    g_cur[MAXN];
__device__ int    g_es[MAXE];
__device__ int    g_btot[128];
__device__ int    g_bex[128];

__device__ __forceinline__ float leaky_f(float x) { return x >= 0.f ? x : 0.01f * x; }

__device__ __forceinline__ uint32_t f2tf(float f) {
    uint32_t u;
    asm("cvt.rna.tf32.f32 %0, %1;" : "=r"(u) : "f"(f));
    return u;
}

#define MMA_TF32(c, a, b0, b1)                                                   \
    asm volatile("mma.sync.aligned.m16n8k8.row.col.f32.tf32.tf32.f32 "           \
                 "{%0,%1,%2,%3}, {%4,%5,%6,%7}, {%8,%9}, {%0,%1,%2,%3};"         \
                 : "+f"((c)[0]), "+f"((c)[1]), "+f"((c)[2]), "+f"((c)[3])        \
                 : "r"((a)[0]), "r"((a)[1]), "r"((a)[2]), "r"((a)[3]),           \
                   "r"(b0), "r"(b1))

// ---------------------------------------------------------------------------
__global__ void k0_prep(const float* __restrict__ Watt, const float* __restrict__ batt,
                        const float* __restrict__ a)
{
    int k = threadIdx.x;
    float us = 0.f, ud = 0.f;
    for (int o = 0; o < 128; o++) {
        float w = Watt[o * 128 + k];
        us += w * a[o];
        ud += w * a[128 + o];
    }
    g_u[k] = us;
    g_u[128 + k] = ud;

    __shared__ float red[256];
    red[k] = batt[k] * a[k];
    red[128 + k] = batt[k] * a[128 + k];
    __syncthreads();
    if (k == 0) {
        float cs = 0.f, cd = 0.f;
        for (int i = 0; i < 128; i++) { cs += red[i]; cd += red[128 + i]; }
        g_u[256] = cs;
        g_u[257] = cd;
    }
}

// --------------------------- counting sort by dst ---------------------------
__global__ void kz(int N)
{
    int i = blockIdx.x * 256 + threadIdx.x;
    if (i < N) g_cnt[i] = 0;
}

__global__ void kh(const int* __restrict__ dst, int E)
{
    int e = blockIdx.x * 256 + threadIdx.x;
    if (e < E) atomicAdd(&g_cnt[__ldg(dst + e)], 1);
}

__global__ __launch_bounds__(1024) void scanA(int N)
{
    __shared__ int sh[1024];
    int tid = threadIdx.x;
    int g = blockIdx.x * 1024 + tid;
    int v = (g < N) ? g_cnt[g] : 0;
    sh[tid] = v;
    __syncthreads();
    for (int d = 1; d < 1024; d <<= 1) {
        int t = (tid >= d) ? sh[tid - d] : 0;
        __syncthreads();
        sh[tid] += t;
        __syncthreads();
    }
    if (g < N) g_off[g] = sh[tid] - v;
    if (tid == 1023) g_btot[blockIdx.x] = sh[1023];
}

__global__ void scanB(int N, int NB)
{
    __shared__ int s[128];
    int tid = threadIdx.x;
    if (tid < NB) s[tid] = g_btot[tid];
    __syncthreads();
    if (tid == 0) {
        int run = 0;
        for (int i = 0; i < NB; i++) { int c = s[i]; s[i] = run; run += c; }
        g_off[N] = run;
    }
    __syncthreads();
    if (tid < NB) g_bex[tid] = s[tid];
}

__global__ __launch_bounds__(1024) void scanC(int N)
{
    int g = blockIdx.x * 1024 + threadIdx.x;
    if (g < N) {
        int o = g_off[g] + g_bex[blockIdx.x];
        g_off[g] = o;
        g_cur[g] = o;
    }
}

__global__ void kscat(const int* __restrict__ src, const int* __restrict__ dst, int E)
{
    int e = blockIdx.x * 256 + threadIdx.x;
    if (e < E) {
        int d = __ldg(dst + e);
        int pos = atomicAdd(&g_cur[d], 1);
        g_es[pos] = __ldg(src + e);
    }
}

// ---------------------------------------------------------------------------
// ks: attention scalars, one warp per node (coalesced float4 reads of X).
// ---------------------------------------------------------------------------
__global__ __launch_bounds__(256) void ks_scal(const float* __restrict__ X, int N)
{
    int n = blockIdx.x * 8 + (threadIdx.x >> 5);
    if (n >= N) return;
    int lane = threadIdx.x & 31;
    float4 v = ((const float4*)X)[n * 32 + lane];
    float4 us = ((const float4*)g_u)[lane];
    float4 ud = ((const float4*)(g_u + 128))[lane];
    float as = v.x * us.x + v.y * us.y + v.z * us.z + v.w * us.w;
    float ad = v.x * ud.x + v.y * ud.y + v.z * ud.z + v.w * ud.w;
    #pragma unroll
    for (int o = 16; o > 0; o >>= 1) {
        as += __shfl_xor_sync(0xffffffffu, as, o);
        ad += __shfl_xor_sync(0xffffffffu, ad, o);
    }
    if (lane == 0) {
        g_ssrc[n] = as + g_u[256];
        g_sdst[n] = ad + g_u[257];
    }
}

// ---------------------------------------------------------------------------
// tf32 GEMM, fragment-ordered smem.
// Element k of a row is stored at (k>>3)*8 + (k&3)*2 + ((k&7)>>2).
// Thread (gid,tig) then loads its (k0+tig, k0+tig+4) pair as one uint2.
// ---------------------------------------------------------------------------
#define GEMM_SMEM (2 * 128 * TS * 4)
#define K4_SMEM   (3 * 128 * TS * 4)

__global__ __launch_bounds__(256) void k1_msg(const float* __restrict__ X,
                                              const float* __restrict__ W1,
                                              const float* __restrict__ b1,
                                              int N)
{
    extern __shared__ uint32_t smu[];
    uint32_t* Xs = smu;
    uint32_t* Ws = smu + 128 * TS;
    const int tid = threadIdx.x;
    const int bn = blockIdx.x * 128;

    for (int i = tid; i < 128 * 32; i += 256) {
        int r = i >> 5, c4 = i & 31;
        int n = bn + r;
        float4 v = (n < N) ? ((const float4*)X)[n * 32 + c4] : make_float4(0.f, 0.f, 0.f, 0.f);
        uint32_t* p = Xs + r * TS + (c4 >> 1) * 8 + (c4 & 1);
        p[0] = f2tf(v.x); p[2] = f2tf(v.y); p[4] = f2tf(v.z); p[6] = f2tf(v.w);
    }
    for (int i = tid; i < 128 * 32; i += 256) {
        int o = i >> 5, c4 = i & 31;
        float4 v = *(const float4*)(W1 + o * 128 + c4 * 4);
        uint32_t* p = Ws + o * TS + (c4 >> 1) * 8 + (c4 & 1);
        p[0] = f2tf(v.x); p[2] = f2tf(v.y); p[4] = f2tf(v.z); p[6] = f2tf(v.w);
    }
    __syncthreads();

    const int wid = tid >> 5, lane = tid & 31;
    const int gid = lane >> 2, tig = lane & 3;
    const int mb = (wid >> 1) * 32;
    const int nb = (wid & 1) * 64;

    float acc[2][8][4];
    #pragma unroll
    for (int m = 0; m < 2; m++)
        #pragma unroll
        for (int n = 0; n < 8; n++)
            #pragma unroll
            for (int j = 0; j < 4; j++) acc[m][n][j] = 0.f;

    #pragma unroll 4
    for (int ks = 0; ks < 16; ks++) {
        const int kb = ks * 8 + tig * 2;
        uint32_t a[2][4];
        #pragma unroll
        for (int mt = 0; mt < 2; mt++) {
            int r0 = mb + mt * 16 + gid;
            uint2 ua = *(const uint2*)(Xs + r0 * TS + kb);
            uint2 ub = *(const uint2*)(Xs + (r0 + 8) * TS + kb);
            a[mt][0] = ua.x; a[mt][1] = ub.x; a[mt][2] = ua.y; a[mt][3] = ub.y;
        }
        #pragma unroll
        for (int nt = 0; nt < 8; nt++) {
            int o = nb + nt * 8 + gid;
            uint2 w = *(const uint2*)(Ws + o * TS + kb);
            MMA_TF32(acc[0][nt], a[0], w.x, w.y);
            MMA_TF32(acc[1][nt], a[1], w.x, w.y);
        }
    }

    #pragma unroll
    for (int nt = 0; nt < 8; nt++) {
        int col = nb + nt * 8 + tig * 2;
        float2 bb = *(const float2*)(b1 + col);
        #pragma unroll
        for (int mt = 0; mt < 2; mt++) {
            int row = bn + mb + mt * 16 + gid;
            if (row < N)
                *(__half2*)(g_hmsg + row * 128 + col) =
                    __floats2half2_rn(acc[mt][nt][0] + bb.x, acc[mt][nt][1] + bb.y);
            if (row + 8 < N)
                *(__half2*)(g_hmsg + (row + 8) * 128 + col) =
                    __floats2half2_rn(acc[mt][nt][2] + bb.x, acc[mt][nt][3] + bb.y);
        }
    }
}

// ---------------------------------------------------------------------------
// kagg: one warp per dst node; fp16 gather (uint2/lane), fp32 accumulate.
// ---------------------------------------------------------------------------
__global__ __launch_bounds__(256) void kagg(int N)
{
    const int d = blockIdx.x * 8 + (threadIdx.x >> 5);
    if (d >= N) return;
    const int lane = threadIdx.x & 31;
    const int rs = g_off[d], re = g_off[d + 1];
    const float sdst_d = g_sdst[d];

    float4 acc = make_float4(0.f, 0.f, 0.f, 0.f);
    float wsum = 0.f;

    for (int c = rs; c < re; c += 32) {
        int cnt = re - c; if (cnt > 32) cnt = 32;
        int s = (lane < cnt) ? g_es[c + lane] : 0;
        float w = 0.f;
        if (lane < cnt) w = expf(leaky_f(g_ssrc[s] + sdst_d));
        wsum += w;

        int j = 0;
        for (; j + 4 <= cnt; j += 4) {
            int s0 = __shfl_sync(0xffffffffu, s, j);
            int s1 = __shfl_sync(0xffffffffu, s, j + 1);
            int s2 = __shfl_sync(0xffffffffu, s, j + 2);
            int s3 = __shfl_sync(0xffffffffu, s, j + 3);
            float w0 = __shfl_sync(0xffffffffu, w, j);
            float w1 = __shfl_sync(0xffffffffu, w, j + 1);
            float w2 = __shfl_sync(0xffffffffu, w, j + 2);
            float w3 = __shfl_sync(0xffffffffu, w, j + 3);
            uint2 u0 = ((const uint2*)(g_hmsg + s0 * 128))[lane];
            uint2 u1 = ((const uint2*)(g_hmsg + s1 * 128))[lane];
            uint2 u2 = ((const uint2*)(g_hmsg + s2 * 128))[lane];
            uint2 u3 = ((const uint2*)(g_hmsg + s3 * 128))[lane];
            float2 a0 = __half22float2(*(__half2*)&u0.x), b0 = __half22float2(*(__half2*)&u0.y);
            float2 a1 = __half22float2(*(__half2*)&u1.x), b1 = __half22float2(*(__half2*)&u1.y);
            float2 a2 = __half22float2(*(__half2*)&u2.x), b2 = __half22float2(*(__half2*)&u2.y);
            float2 a3 = __half22float2(*(__half2*)&u3.x), b3 = __half22float2(*(__half2*)&u3.y);
            acc.x += w0 * a0.x + w1 * a1.x + w2 * a2.x + w3 * a3.x;
            acc.y += w0 * a0.y + w1 * a1.y + w2 * a2.y + w3 * a3.y;
            acc.z += w0 * b0.x + w1 * b1.x + w2 * b2.x + w3 * b3.x;
            acc.w += w0 * b0.y + w1 * b1.y + w2 * b2.y + w3 * b3.y;
        }
        for (; j < cnt; j++) {
            int sj = __shfl_sync(0xffffffffu, s, j);
            float wj = __shfl_sync(0xffffffffu, w, j);
            uint2 u = ((const uint2*)(g_hmsg + sj * 128))[lane];
            float2 a0 = __half22float2(*(__half2*)&u.x), b0 = __half22float2(*(__half2*)&u.y);
            acc.x += wj * a0.x; acc.y += wj * a0.y;
            acc.z += wj * b0.x; acc.w += wj * b0.y;
        }
    }

    #pragma unroll
    for (int o = 16; o > 0; o >>= 1) wsum += __shfl_xor_sync(0xffffffffu, wsum, o);
    float inv = 1.f / (wsum + 1e-9f);
    acc.x *= inv; acc.y *= inv; acc.z *= inv; acc.w *= inv;
    ((float4*)g_hneigh)[d * 32 + lane] = acc;
}

// ---------------------------------------------------------------------------
__global__ __launch_bounds__(256) void k4_out(const float* __restrict__ X,
                                              const float* __restrict__ W2,
                                              const float* __restrict__ b2,
                                              float* __restrict__ out, int N)
{
    extern __shared__ uint32_t smu[];
    uint32_t* Ps = smu;                         // (X*h) tf32 fragment order
    uint32_t* Ws = smu + 128 * TS;              // W2 tf32 fragment order
    float* Ss = (float*)(smu + 2 * 128 * TS);   // (X+h) fp32 natural order
    const int tid = threadIdx.x;
    const int bn = blockIdx.x * 128;

    for (int i = tid; i < 128 * 32; i += 256) {
        int r = i >> 5, c4 = i & 31;
        int n = bn + r;
        float4 x = (n < N) ? ((const float4*)X)[n * 32 + c4] : make_float4(0.f, 0.f, 0.f, 0.f);
        float4 h = (n < N) ? ((const float4*)g_hneigh)[n * 32 + c4] : make_float4(0.f, 0.f, 0.f, 0.f);
        *(float4*)(Ss + r * TS + c4 * 4) = make_float4(x.x + h.x, x.y + h.y, x.z + h.z, x.w + h.w);
        uint32_t* p = Ps + r * TS + (c4 >> 1) * 8 + (c4 & 1);
        p[0] = f2tf(x.x * h.x); p[2] = f2tf(x.y * h.y);
        p[4] = f2tf(x.z * h.z); p[6] = f2tf(x.w * h.w);
    }
    for (int i = tid; i < 128 * 32; i += 256) {
        int o = i >> 5, c4 = i & 31;
        float4 v = *(const float4*)(W2 + o * 128 + c4 * 4);
        uint32_t* p = Ws + o * TS + (c4 >> 1) * 8 + (c4 & 1);
        p[0] = f2tf(v.x); p[2] = f2tf(v.y); p[4] = f2tf(v.z); p[6] = f2tf(v.w);
    }
    __syncthreads();

    const int wid = tid >> 5, lane = tid & 31;
    const int gid = lane >> 2, tig = lane & 3;
    const int mb = (wid >> 1) * 32;
    const int nb = (wid & 1) * 64;

    float acc[2][8][4];
    #pragma unroll
    for (int m = 0; m < 2; m++)
        #pragma unroll
        for (int n = 0; n < 8; n++)
            #pragma unroll
            for (int j = 0; j < 4; j++) acc[m][n][j] = 0.f;

    #pragma unroll 4
    for (int ks = 0; ks < 16; ks++) {
        const int kb = ks * 8 + tig * 2;
        uint32_t a[2][4];
        #pragma unroll
        for (int mt = 0; mt < 2; mt++) {
            int r0 = mb + mt * 16 + gid;
            uint2 ua = *(const uint2*)(Ps + r0 * TS + kb);
            uint2 ub = *(const uint2*)(Ps + (r0 + 8) * TS + kb);
            a[mt][0] = ua.x; a[mt][1] = ub.x; a[mt][2] = ua.y; a[mt][3] = ub.y;
        }
        #pragma unroll
        for (int nt = 0; nt < 8; nt++) {
            int o = nb + nt * 8 + gid;
            uint2 w = *(const uint2*)(Ws + o * TS + kb);
            MMA_TF32(acc[0][nt], a[0], w.x, w.y);
            MMA_TF32(acc[1][nt], a[1], w.x, w.y);
        }
    }

    #pragma unroll
    for (int nt = 0; nt < 8; nt++) {
        int col = nb + nt * 8 + tig * 2;
        float2 bb = *(const float2*)(b2 + col);
        #pragma unroll
        for (int mt = 0; mt < 2; mt++) {
            #pragma unroll
            for (int half = 0; half < 2; half++) {
                int rl = mb + mt * 16 + gid + half * 8;
                int row = bn + rl;
                if (row < N) {
                    float2 t1 = *(const float2*)(Ss + rl * TS + col);
                    float r0 = t1.x + acc[mt][nt][half * 2] + bb.x;
                    float r1 = t1.y + acc[mt][nt][half * 2 + 1] + bb.y;
                    *(float2*)(out + row * 128 + col) =
                        make_float2(leaky_f(r0), leaky_f(r1));
                }
            }
        }
    }
}

// ---------------------------------------------------------------------------
extern "C" void kernel_launch(void* const* d_in, const int* in_sizes, int n_in,
                              void* d_out, int out_size)
{
    const int*   indices = (const int*)d_in[0];
    const float* X       = (const float*)d_in[1];
    const float* Watt    = (const float*)d_in[3];
    const float* batt    = (const float*)d_in[4];
    const float* W1      = (const float*)d_in[5];
    const float* b1      = (const float*)d_in[6];
    const float* W2      = (const float*)d_in[7];
    const float* b2      = (const float*)d_in[8];
    const float* a       = (const float*)d_in[9];
    float* out = (float*)d_out;

    const int E = in_sizes[0] / 2;
    const int N = in_sizes[1] / 128;
    const int* src = indices;
    const int* dst = indices + E;
    const int NB = (N + 1023) / 1024;

    cudaFuncSetAttribute(k1_msg, cudaFuncAttributeMaxDynamicSharedMemorySize, GEMM_SMEM);
    cudaFuncSetAttribute(k4_out, cudaFuncAttributeMaxDynamicSharedMemorySize, K4_SMEM);

    k0_prep<<<1, 128>>>(Watt, batt, a);
    kz<<<(N + 255) / 256, 256>>>(N);
    kh<<<(E + 255) / 256, 256>>>(dst, E);
    scanA<<<NB, 1024>>>(N);
    scanB<<<1, 128>>>(N, NB);
    scanC<<<NB, 1024>>>(N);
    kscat<<<(E + 255) / 256, 256>>>(src, dst, E);
    ks_scal<<<(N + 7) / 8, 256>>>(X, N);
    k1_msg<<<(N + 127) / 128, 256, GEMM_SMEM>>>(X, W1, b1, N);
    kagg<<<(N + 7) / 8, 256>>>(N);
    k4_out<<<(N + 127) / 128, 256, K4_SMEM>>>(X, W2, b2, out, N);
}